// round 1
// baseline (speedup 1.0000x reference)
#include <cuda_runtime.h>
#include <cuda_bf16.h>
#include <math.h>

#define N_ROIS      2000
#define POOL        7
#define C_FEAT      256
#define KDIM        (C_FEAT * POOL * POOL)   // 12544
#define HID         1024
#define NUM_CLASSES 81
#define NBOX        (NUM_CLASSES * 4)        // 324
#define BN_EPS      0.001f
#define IMG_DIM     1024.0f

// ---------------- scratch (device globals; no allocation allowed) ----------
__device__ float g_pooled[N_ROIS * KDIM];          // ~100 MB
__device__ float g_h1[N_ROIS * HID];
__device__ float g_sh[N_ROIS * HID];
__device__ float g_scale1[HID], g_shift1[HID];
__device__ float g_scale2[HID], g_shift2[HID];

// ---------------- fold BN (+conv bias) into scale/shift --------------------
__global__ void fuse_bn_kernel(const float* __restrict__ cb1, const float* __restrict__ g1,
                               const float* __restrict__ b1, const float* __restrict__ m1,
                               const float* __restrict__ v1,
                               const float* __restrict__ cb2, const float* __restrict__ g2,
                               const float* __restrict__ b2, const float* __restrict__ m2,
                               const float* __restrict__ v2)
{
    int i = blockIdx.x * blockDim.x + threadIdx.x;
    if (i < HID) {
        float s = g1[i] * rsqrtf(v1[i] + BN_EPS);
        g_scale1[i] = s;
        g_shift1[i] = (cb1[i] - m1[i]) * s + b1[i];
    } else if (i < 2 * HID) {
        int j = i - HID;
        float s = g2[j] * rsqrtf(v2[j] + BN_EPS);
        g_scale2[j] = s;
        g_shift2[j] = (cb2[j] - m2[j]) * s + b2[j];
    }
}

// ---------------- ROI-Align pooling (one block per ROI) --------------------
__global__ void pool_kernel(const float* __restrict__ p2, const float* __restrict__ p3,
                            const float* __restrict__ p4, const float* __restrict__ p5,
                            const float* __restrict__ rois)
{
    int n = blockIdx.x;
    int tid = threadIdx.x;

    float x1 = rois[4 * n + 0];
    float y1 = rois[4 * n + 1];
    float x2 = rois[4 * n + 2];
    float y2 = rois[4 * n + 3];

    // level selection: clip(round(log2(sqrt(area)/224)) + 4, 2, 5)
    float area = (y2 - y1) * (x2 - x1);
    float lv = rintf(log2f(sqrtf(area) / 224.0f)) + 4.0f;
    lv = fminf(fmaxf(lv, 2.0f), 5.0f);
    int lvl = (int)lv;

    const float* fmap;
    int H;
    if (lvl == 2)      { fmap = p2; H = 256; }
    else if (lvl == 3) { fmap = p3; H = 128; }
    else if (lvl == 4) { fmap = p4; H = 64;  }
    else               { fmap = p5; H = 32;  }

    // normalized box in (y1,x1,y2,x2)
    float ny1 = y1 / IMG_DIM, nx1 = x1 / IMG_DIM;
    float ny2 = y2 / IMG_DIM, nx2 = x2 / IMG_DIM;

    __shared__ float s_ly[POOL], s_lx[POOL];
    __shared__ int   s_y0[POOL], s_y1[POOL], s_x0[POOL], s_x1[POOL];

    if (tid < POOL) {
        int i = tid;
        float t = (float)i / (float)(POOL - 1);
        float Hm1 = (float)(H - 1);
        float ys = ny1 * Hm1 + t * ((ny2 - ny1) * Hm1);
        float y0 = floorf(ys);
        s_ly[i] = ys - y0;
        int y0i = min(max((int)y0, 0), H - 1);
        s_y0[i] = y0i;
        s_y1[i] = min(y0i + 1, H - 1);
    } else if (tid < 2 * POOL) {
        int i = tid - POOL;
        float t = (float)i / (float)(POOL - 1);
        float Wm1 = (float)(H - 1);   // square maps
        float xs = nx1 * Wm1 + t * ((nx2 - nx1) * Wm1);
        float x0 = floorf(xs);
        s_lx[i] = xs - x0;
        int x0i = min(max((int)x0, 0), H - 1);
        s_x0[i] = x0i;
        s_x1[i] = min(x0i + 1, H - 1);
    }
    __syncthreads();

    int HW = H * H;
    float* out = g_pooled + (size_t)n * KDIM;

    for (int idx = tid; idx < KDIM; idx += blockDim.x) {
        int c  = idx / (POOL * POOL);
        int p  = idx % (POOL * POOL);
        int iy = p / POOL;
        int ix = p % POOL;
        const float* f = fmap + (size_t)c * HW;
        int y0 = s_y0[iy], y1i = s_y1[iy];
        int x0 = s_x0[ix], x1i = s_x1[ix];
        float fy = s_ly[iy], fx = s_lx[ix];
        float v00 = f[y0  * H + x0 ];
        float v01 = f[y0  * H + x1i];
        float v10 = f[y1i * H + x0 ];
        float v11 = f[y1i * H + x1i];
        out[idx] = v00 * (1.f - fy) * (1.f - fx)
                 + v01 * (1.f - fy) * fx
                 + v10 * fy * (1.f - fx)
                 + v11 * fy * fx;
    }
}

// ---------------- tiled SGEMM: C = relu/lin((A * B^T) * scale + shift) -----
// A [M,K] row-major, B [N,K] row-major; 64x64 tile, 256 threads, 4x4/thread.
#define TM 64
#define TN 64
#define TK 16

__global__ __launch_bounds__(256)
void sgemm_epi_kernel(const float* __restrict__ A, const float* __restrict__ B,
                      const float* __restrict__ scale, const float* __restrict__ shift,
                      float* __restrict__ C, int M, int N, int K)
{
    __shared__ float As[TM][TK + 1];       // [m][k]
    __shared__ float Bs[TK][TN + 4];       // [k][n]

    int tid = threadIdx.x;
    int tx = tid % 16;
    int ty = tid / 16;
    int m0 = blockIdx.y * TM;
    int n0 = blockIdx.x * TN;

    int lm = tid / 4;                // 0..63
    int lk = (tid % 4) * 4;          // 0,4,8,12

    float acc[4][4];
#pragma unroll
    for (int i = 0; i < 4; i++)
#pragma unroll
        for (int j = 0; j < 4; j++) acc[i][j] = 0.f;

    for (int k0 = 0; k0 < K; k0 += TK) {
        // A tile
        int am = m0 + lm;
        if (am < M) {
            float4 a4 = *reinterpret_cast<const float4*>(&A[(size_t)am * K + k0 + lk]);
            As[lm][lk + 0] = a4.x; As[lm][lk + 1] = a4.y;
            As[lm][lk + 2] = a4.z; As[lm][lk + 3] = a4.w;
        } else {
            As[lm][lk + 0] = 0.f; As[lm][lk + 1] = 0.f;
            As[lm][lk + 2] = 0.f; As[lm][lk + 3] = 0.f;
        }
        // B tile (N is a multiple of 64)
        float4 b4 = *reinterpret_cast<const float4*>(&B[(size_t)(n0 + lm) * K + k0 + lk]);
        Bs[lk + 0][lm] = b4.x; Bs[lk + 1][lm] = b4.y;
        Bs[lk + 2][lm] = b4.z; Bs[lk + 3][lm] = b4.w;
        __syncthreads();

#pragma unroll
        for (int k = 0; k < TK; k++) {
            float a[4], b[4];
#pragma unroll
            for (int i = 0; i < 4; i++) a[i] = As[ty * 4 + i][k];
#pragma unroll
            for (int j = 0; j < 4; j++) b[j] = Bs[k][tx * 4 + j];
#pragma unroll
            for (int i = 0; i < 4; i++)
#pragma unroll
                for (int j = 0; j < 4; j++)
                    acc[i][j] += a[i] * b[j];
        }
        __syncthreads();
    }

#pragma unroll
    for (int i = 0; i < 4; i++) {
        int row = m0 + ty * 4 + i;
        if (row >= M) continue;
#pragma unroll
        for (int j = 0; j < 4; j++) {
            int col = n0 + tx * 4 + j;
            float v = acc[i][j] * scale[col] + shift[col];
            v = fmaxf(v, 0.f);   // both dense layers use ReLU
            C[(size_t)row * N + col] = v;
        }
    }
}

// ---------------- head: logits + softmax + bbox (one block per ROI) --------
__global__ __launch_bounds__(128)
void head_kernel(const float* __restrict__ sh,
                 const float* __restrict__ lw, const float* __restrict__ lb,
                 const float* __restrict__ bw, const float* __restrict__ bb,
                 float* __restrict__ out)
{
    int n = blockIdx.x;
    int tid = threadIdx.x;
    int lane = tid & 31;
    int wid = tid >> 5;

    __shared__ float s_row[HID];
    __shared__ float s_log[NUM_CLASSES];

    for (int k = tid; k < HID; k += 128) s_row[k] = sh[(size_t)n * HID + k];
    __syncthreads();

    const int NOUT = NUM_CLASSES + NBOX;   // 405
    for (int o = wid; o < NOUT; o += 4) {
        const float* w = (o < NUM_CLASSES) ? (lw + (size_t)o * HID)
                                           : (bw + (size_t)(o - NUM_CLASSES) * HID);
        float sum = 0.f;
        for (int k = lane; k < HID; k += 32) sum += s_row[k] * w[k];
#pragma unroll
        for (int off = 16; off > 0; off >>= 1)
            sum += __shfl_xor_sync(0xFFFFFFFFu, sum, off);
        if (lane == 0) {
            if (o < NUM_CLASSES) {
                float v = sum + lb[o];
                s_log[o] = v;
                out[(size_t)n * NUM_CLASSES + o] = v;                      // logits
            } else {
                int ob = o - NUM_CLASSES;
                float v = sum + bb[ob];
                out[(size_t)(2 * N_ROIS * NUM_CLASSES) + (size_t)n * NBOX + ob] = v;  // bbox
            }
        }
    }
    __syncthreads();

    if (tid == 0) {
        float mx = -INFINITY;
        for (int o = 0; o < NUM_CLASSES; o++) mx = fmaxf(mx, s_log[o]);
        float s = 0.f;
        float e[NUM_CLASSES];
        for (int o = 0; o < NUM_CLASSES; o++) { e[o] = expf(s_log[o] - mx); s += e[o]; }
        float inv = 1.f / s;
        float* probs = out + (size_t)N_ROIS * NUM_CLASSES;
        for (int o = 0; o < NUM_CLASSES; o++)
            probs[(size_t)n * NUM_CLASSES + o] = e[o] * inv;
    }
}

// ---------------- launch ---------------------------------------------------
extern "C" void kernel_launch(void* const* d_in, const int* in_sizes, int n_in,
                              void* d_out, int out_size)
{
    const float* p2       = (const float*)d_in[0];
    const float* p3       = (const float*)d_in[1];
    const float* p4       = (const float*)d_in[2];
    const float* p5       = (const float*)d_in[3];
    const float* rois     = (const float*)d_in[4];
    const float* conv1_w  = (const float*)d_in[5];
    const float* conv1_b  = (const float*)d_in[6];
    const float* bn1_g    = (const float*)d_in[7];
    const float* bn1_b    = (const float*)d_in[8];
    const float* bn1_m    = (const float*)d_in[9];
    const float* bn1_v    = (const float*)d_in[10];
    const float* conv2_w  = (const float*)d_in[11];
    const float* conv2_b  = (const float*)d_in[12];
    const float* bn2_g    = (const float*)d_in[13];
    const float* bn2_b    = (const float*)d_in[14];
    const float* bn2_m    = (const float*)d_in[15];
    const float* bn2_v    = (const float*)d_in[16];
    const float* logits_w = (const float*)d_in[17];
    const float* logits_b = (const float*)d_in[18];
    const float* bbox_w   = (const float*)d_in[19];
    const float* bbox_b   = (const float*)d_in[20];
    float* out = (float*)d_out;

    float *pooled, *h1, *shbuf, *sc1, *sf1, *sc2, *sf2;
    cudaGetSymbolAddress((void**)&pooled, g_pooled);
    cudaGetSymbolAddress((void**)&h1,     g_h1);
    cudaGetSymbolAddress((void**)&shbuf,  g_sh);
    cudaGetSymbolAddress((void**)&sc1,    g_scale1);
    cudaGetSymbolAddress((void**)&sf1,    g_shift1);
    cudaGetSymbolAddress((void**)&sc2,    g_scale2);
    cudaGetSymbolAddress((void**)&sf2,    g_shift2);

    fuse_bn_kernel<<<8, 256>>>(conv1_b, bn1_g, bn1_b, bn1_m, bn1_v,
                               conv2_b, bn2_g, bn2_b, bn2_m, bn2_v);

    pool_kernel<<<N_ROIS, 256>>>(p2, p3, p4, p5, rois);

    {
        dim3 grid(HID / TN, (N_ROIS + TM - 1) / TM);
        sgemm_epi_kernel<<<grid, 256>>>(pooled, conv1_w, sc1, sf1, h1,
                                        N_ROIS, HID, KDIM);
    }
    {
        dim3 grid(HID / TN, (N_ROIS + TM - 1) / TM);
        sgemm_epi_kernel<<<grid, 256>>>(h1, conv2_w, sc2, sf2, shbuf,
                                        N_ROIS, HID, HID);
    }

    head_kernel<<<N_ROIS, 128>>>(shbuf, logits_w, logits_b, bbox_w, bbox_b, out);
}

// round 4
// speedup vs baseline: 3.3516x; 3.3516x over previous
#include <cuda_runtime.h>
#include <cuda_bf16.h>
#include <math.h>
#include <stdint.h>

#define N_ROIS      2000
#define MPAD        2048
#define POOL        7
#define C_FEAT      256
#define KDIM        (C_FEAT * POOL * POOL)   // 12544
#define K1P         (3 * KDIM)               // 37632
#define HID         1024
#define K2P         (3 * HID)                // 3072
#define NUM_CLASSES 81
#define NBOX        (NUM_CLASSES * 4)
#define BN_EPS      0.001f
#define IMG_DIM     1024.0f

// ---------------- scratch (device globals; zero-initialized) ---------------
__device__ __align__(128) __nv_bfloat16 g_A1[(size_t)MPAD * K1P];   // pooled split [h|l|h]
__device__ __align__(128) __nv_bfloat16 g_B1[(size_t)HID * K1P];    // conv1_w split [h|h|l]
__device__ __align__(128) __nv_bfloat16 g_A2[(size_t)MPAD * K2P];   // h1 split [h|l|h]
__device__ __align__(128) __nv_bfloat16 g_B2[(size_t)HID * K2P];    // conv2_w split [h|h|l]
__device__ float g_sh[N_ROIS * HID];
__device__ float g_scale1[HID], g_shift1[HID];
__device__ float g_scale2[HID], g_shift2[HID];

// ---------------- helpers ---------------------------------------------------
__device__ __forceinline__ uint32_t smem_u32(const void* p) {
    uint32_t a;
    asm("{ .reg .u64 t; cvta.to.shared.u64 t, %1; cvt.u32.u64 %0, t; }" : "=r"(a) : "l"(p));
    return a;
}
__device__ __forceinline__ void split_bf16(float v, __nv_bfloat16& h, __nv_bfloat16& l) {
    h = __float2bfloat16(v);
    l = __float2bfloat16(v - __bfloat162float(h));
}
__device__ __forceinline__ void cp16(uint32_t sa, const void* ga) {
    asm volatile("cp.async.cg.shared.global [%0], [%1], 16;" :: "r"(sa), "l"(ga));
}
__device__ __forceinline__ void cp_commit() {
    asm volatile("cp.async.commit_group;" ::: "memory");
}
__device__ __forceinline__ void cp_wait2() {
    asm volatile("cp.async.wait_group 2;" ::: "memory");
}
__device__ __forceinline__ void ldsm_x4(uint32_t& r0, uint32_t& r1, uint32_t& r2, uint32_t& r3,
                                        uint32_t addr) {
    asm volatile("ldmatrix.sync.aligned.m8n8.x4.shared.b16 {%0,%1,%2,%3}, [%4];"
                 : "=r"(r0), "=r"(r1), "=r"(r2), "=r"(r3) : "r"(addr));
}
__device__ __forceinline__ void mma_bf16(float* d, const uint32_t* a, const uint32_t* b) {
    asm volatile(
        "mma.sync.aligned.m16n8k16.row.col.f32.bf16.bf16.f32 "
        "{%0,%1,%2,%3}, {%4,%5,%6,%7}, {%8,%9}, {%0,%1,%2,%3};"
        : "+f"(d[0]), "+f"(d[1]), "+f"(d[2]), "+f"(d[3])
        : "r"(a[0]), "r"(a[1]), "r"(a[2]), "r"(a[3]), "r"(b[0]), "r"(b[1]));
}

// ---------------- fold BN (+conv bias) into scale/shift --------------------
__global__ void fuse_bn_kernel(const float* __restrict__ cb1, const float* __restrict__ g1,
                               const float* __restrict__ b1, const float* __restrict__ m1,
                               const float* __restrict__ v1,
                               const float* __restrict__ cb2, const float* __restrict__ g2,
                               const float* __restrict__ b2, const float* __restrict__ m2,
                               const float* __restrict__ v2)
{
    int i = blockIdx.x * blockDim.x + threadIdx.x;
    if (i < HID) {
        float s = g1[i] * rsqrtf(v1[i] + BN_EPS);
        g_scale1[i] = s;
        g_shift1[i] = (cb1[i] - m1[i]) * s + b1[i];
    } else if (i < 2 * HID) {
        int j = i - HID;
        float s = g2[j] * rsqrtf(v2[j] + BN_EPS);
        g_scale2[j] = s;
        g_shift2[j] = (cb2[j] - m2[j]) * s + b2[j];
    }
}

// ------- weight split: W[N,K] fp32 -> [N,3K] bf16 as [hi | hi | lo] --------
__global__ void convw_kernel(const float* __restrict__ W, __nv_bfloat16* __restrict__ out,
                             int K, long total)
{
    long idx = (long)blockIdx.x * blockDim.x + threadIdx.x;
    long stride = (long)gridDim.x * blockDim.x;
    for (; idx < total; idx += stride) {
        int n = (int)(idx / K);
        int k = (int)(idx % K);
        __nv_bfloat16 h, l;
        split_bf16(W[idx], h, l);
        __nv_bfloat16* row = out + (size_t)n * (3 * K);
        row[k] = h;
        row[k + K] = h;          // FIX: hi here
        row[k + 2 * K] = l;      // FIX: lo here -> A[h|l|h]·B[h|h|l] = hh + lh + hl
    }
}

// ---------------- ROI-Align pooling -> bf16 split A1 [h|l|h] ---------------
__global__ void pool_kernel(const float* __restrict__ p2, const float* __restrict__ p3,
                            const float* __restrict__ p4, const float* __restrict__ p5,
                            const float* __restrict__ rois)
{
    int n = blockIdx.x;
    int tid = threadIdx.x;

    float x1 = rois[4 * n + 0];
    float y1 = rois[4 * n + 1];
    float x2 = rois[4 * n + 2];
    float y2 = rois[4 * n + 3];

    float area = (y2 - y1) * (x2 - x1);
    float lv = rintf(log2f(sqrtf(area) / 224.0f)) + 4.0f;
    lv = fminf(fmaxf(lv, 2.0f), 5.0f);
    int lvl = (int)lv;

    const float* fmap;
    int H;
    if (lvl == 2)      { fmap = p2; H = 256; }
    else if (lvl == 3) { fmap = p3; H = 128; }
    else if (lvl == 4) { fmap = p4; H = 64;  }
    else               { fmap = p5; H = 32;  }

    float ny1 = y1 / IMG_DIM, nx1 = x1 / IMG_DIM;
    float ny2 = y2 / IMG_DIM, nx2 = x2 / IMG_DIM;

    __shared__ float s_ly[POOL], s_lx[POOL];
    __shared__ int   s_y0[POOL], s_y1[POOL], s_x0[POOL], s_x1[POOL];

    if (tid < POOL) {
        int i = tid;
        float t = (float)i / (float)(POOL - 1);
        float Hm1 = (float)(H - 1);
        float ys = ny1 * Hm1 + t * ((ny2 - ny1) * Hm1);
        float y0 = floorf(ys);
        s_ly[i] = ys - y0;
        int y0i = min(max((int)y0, 0), H - 1);
        s_y0[i] = y0i;
        s_y1[i] = min(y0i + 1, H - 1);
    } else if (tid < 2 * POOL) {
        int i = tid - POOL;
        float t = (float)i / (float)(POOL - 1);
        float Wm1 = (float)(H - 1);
        float xs = nx1 * Wm1 + t * ((nx2 - nx1) * Wm1);
        float x0 = floorf(xs);
        s_lx[i] = xs - x0;
        int x0i = min(max((int)x0, 0), H - 1);
        s_x0[i] = x0i;
        s_x1[i] = min(x0i + 1, H - 1);
    }
    __syncthreads();

    int HW = H * H;
    __nv_bfloat16* arow = g_A1 + (size_t)n * K1P;

    for (int idx = tid; idx < KDIM; idx += blockDim.x) {
        int c  = idx / (POOL * POOL);
        int p  = idx % (POOL * POOL);
        int iy = p / POOL;
        int ix = p % POOL;
        const float* f = fmap + (size_t)c * HW;
        int y0 = s_y0[iy], y1i = s_y1[iy];
        int x0 = s_x0[ix], x1i = s_x1[ix];
        float fy = s_ly[iy], fx = s_lx[ix];
        float v00 = f[y0  * H + x0 ];
        float v01 = f[y0  * H + x1i];
        float v10 = f[y1i * H + x0 ];
        float v11 = f[y1i * H + x1i];
        float v = v00 * (1.f - fy) * (1.f - fx)
                + v01 * (1.f - fy) * fx
                + v10 * fy * (1.f - fx)
                + v11 * fy * fx;
        __nv_bfloat16 h, l;
        split_bf16(v, h, l);
        arow[idx] = h;
        arow[idx + KDIM] = l;
        arow[idx + 2 * KDIM] = h;
    }
}

// ---------------- HMMA bf16 GEMM: C = relu((A*B^T)*scale+shift) ------------
#define KSTEP       32
#define STAGES      3
#define TILE_BYTES  16384
#define ROW_BYTES   64

__device__ __forceinline__ uint32_t sw_off(int row, int ch) {
    return (uint32_t)(row * ROW_BYTES + ((ch ^ ((row >> 1) & 3)) << 4));
}

__device__ __forceinline__ void load_tile(uint32_t sbase, const __nv_bfloat16* g,
                                          int row0, int ldK, int k0, int tid)
{
#pragma unroll
    for (int j = 0; j < 2; j++) {
        int u = tid + j * 256;
        int row = u >> 2;
        int ch = u & 3;
        cp16(sbase + sw_off(row, ch),
             (const void*)(g + (size_t)(row0 + row) * ldK + k0 + ch * 8));
    }
}

__global__ __launch_bounds__(256)
void gemm_hmma_kernel(const __nv_bfloat16* __restrict__ A, const __nv_bfloat16* __restrict__ B,
                      int Kp,
                      const float* __restrict__ scale, const float* __restrict__ shift,
                      float* __restrict__ Cf, __nv_bfloat16* __restrict__ Cb, int mode)
{
    __shared__ __align__(1024) uint8_t smem[STAGES * TILE_BYTES];

    int tid = threadIdx.x;
    int wid = tid >> 5;
    int lane = tid & 31;
    int wm = wid & 3;
    int wn = wid >> 2;
    int m0 = blockIdx.y * 128;
    int n0 = blockIdx.x * 128;

    uint32_t sb = smem_u32(smem);

    float acc[2][8][4];
#pragma unroll
    for (int i = 0; i < 2; i++)
#pragma unroll
        for (int j = 0; j < 8; j++)
#pragma unroll
            for (int q = 0; q < 4; q++) acc[i][j][q] = 0.f;

    int nk = Kp / KSTEP;

#pragma unroll
    for (int s = 0; s < STAGES; s++) {
        load_tile(sb + s * TILE_BYTES,        A, m0, Kp, s * KSTEP, tid);
        load_tile(sb + s * TILE_BYTES + 8192, B, n0, Kp, s * KSTEP, tid);
        cp_commit();
    }

    int arow = wm * 32 + (lane & 15);
    int ach  = lane >> 4;
    int brow = wn * 64 + (lane & 7) + ((lane & 16) ? 8 : 0);
    int bch  = (lane & 8) ? 1 : 0;

    for (int i = 0; i < nk; i++) {
        cp_wait2();
        __syncthreads();
        uint32_t st = sb + (uint32_t)(i % STAGES) * TILE_BYTES;

#pragma unroll
        for (int ks = 0; ks < 2; ks++) {
            uint32_t a[2][4], b[8][2];
#pragma unroll
            for (int mi = 0; mi < 2; mi++)
                ldsm_x4(a[mi][0], a[mi][1], a[mi][2], a[mi][3],
                        st + sw_off(arow + mi * 16, ach + ks * 2));
#pragma unroll
            for (int nt = 0; nt < 4; nt++)
                ldsm_x4(b[nt * 2][0], b[nt * 2][1], b[nt * 2 + 1][0], b[nt * 2 + 1][1],
                        st + 8192 + sw_off(brow + nt * 16, bch + ks * 2));
#pragma unroll
            for (int mi = 0; mi < 2; mi++)
#pragma unroll
                for (int nj = 0; nj < 8; nj++)
                    mma_bf16(acc[mi][nj], a[mi], b[nj]);
        }

        __syncthreads();
        int j = i + STAGES;
        if (j < nk) {
            load_tile(st,        A, m0, Kp, j * KSTEP, tid);
            load_tile(st + 8192, B, n0, Kp, j * KSTEP, tid);
        }
        cp_commit();
    }

#pragma unroll
    for (int mi = 0; mi < 2; mi++) {
        int rbase = m0 + wm * 32 + mi * 16 + (lane >> 2);
#pragma unroll
        for (int nj = 0; nj < 8; nj++) {
            int c = n0 + wn * 64 + nj * 8 + (lane & 3) * 2;
#pragma unroll
            for (int half = 0; half < 2; half++) {
                int m = rbase + half * 8;
                if (m >= N_ROIS) continue;
                float v0 = acc[mi][nj][half * 2 + 0] * scale[c]     + shift[c];
                float v1 = acc[mi][nj][half * 2 + 1] * scale[c + 1] + shift[c + 1];
                v0 = fmaxf(v0, 0.f);
                v1 = fmaxf(v1, 0.f);
                if (mode == 0) {
                    float2 v = make_float2(v0, v1);
                    *reinterpret_cast<float2*>(&Cf[(size_t)m * HID + c]) = v;
                } else {
                    __nv_bfloat16 h0, l0, h1, l1;
                    split_bf16(v0, h0, l0);
                    split_bf16(v1, h1, l1);
                    __nv_bfloat162 hh; hh.x = h0; hh.y = h1;
                    __nv_bfloat162 ll; ll.x = l0; ll.y = l1;
                    __nv_bfloat16* crow = Cb + (size_t)m * K2P + c;
                    *reinterpret_cast<__nv_bfloat162*>(&crow[0])        = hh;
                    *reinterpret_cast<__nv_bfloat162*>(&crow[HID])      = ll;
                    *reinterpret_cast<__nv_bfloat162*>(&crow[2 * HID])  = hh;
                }
            }
        }
    }
}

// ---------------- head: logits + softmax + bbox ----------------------------
__global__ __launch_bounds__(128)
void head_kernel(const float* __restrict__ sh,
                 const float* __restrict__ lw, const float* __restrict__ lb,
                 const float* __restrict__ bw, const float* __restrict__ bb,
                 float* __restrict__ out)
{
    int n = blockIdx.x;
    int tid = threadIdx.x;
    int lane = tid & 31;
    int wid = tid >> 5;

    __shared__ float s_row[HID];
    __shared__ float s_log[NUM_CLASSES];

    for (int k = tid; k < HID; k += 128) s_row[k] = sh[(size_t)n * HID + k];
    __syncthreads();

    const int NOUT = NUM_CLASSES + NBOX;
    for (int o = wid; o < NOUT; o += 4) {
        const float* w = (o < NUM_CLASSES) ? (lw + (size_t)o * HID)
                                           : (bw + (size_t)(o - NUM_CLASSES) * HID);
        float sum = 0.f;
        for (int k = lane; k < HID; k += 32) sum += s_row[k] * w[k];
#pragma unroll
        for (int off = 16; off > 0; off >>= 1)
            sum += __shfl_xor_sync(0xFFFFFFFFu, sum, off);
        if (lane == 0) {
            if (o < NUM_CLASSES) {
                float v = sum + lb[o];
                s_log[o] = v;
                out[(size_t)n * NUM_CLASSES + o] = v;
            } else {
                int ob = o - NUM_CLASSES;
                float v = sum + bb[ob];
                out[(size_t)(2 * N_ROIS * NUM_CLASSES) + (size_t)n * NBOX + ob] = v;
            }
        }
    }
    __syncthreads();

    if (tid == 0) {
        float mx = -INFINITY;
        for (int o = 0; o < NUM_CLASSES; o++) mx = fmaxf(mx, s_log[o]);
        float s = 0.f;
        float e[NUM_CLASSES];
        for (int o = 0; o < NUM_CLASSES; o++) { e[o] = expf(s_log[o] - mx); s += e[o]; }
        float inv = 1.f / s;
        float* probs = out + (size_t)N_ROIS * NUM_CLASSES;
        for (int o = 0; o < NUM_CLASSES; o++)
            probs[(size_t)n * NUM_CLASSES + o] = e[o] * inv;
    }
}

// ---------------- launch ---------------------------------------------------
extern "C" void kernel_launch(void* const* d_in, const int* in_sizes, int n_in,
                              void* d_out, int out_size)
{
    const float* p2       = (const float*)d_in[0];
    const float* p3       = (const float*)d_in[1];
    const float* p4       = (const float*)d_in[2];
    const float* p5       = (const float*)d_in[3];
    const float* rois     = (const float*)d_in[4];
    const float* conv1_w  = (const float*)d_in[5];
    const float* conv1_b  = (const float*)d_in[6];
    const float* bn1_g    = (const float*)d_in[7];
    const float* bn1_b    = (const float*)d_in[8];
    const float* bn1_m    = (const float*)d_in[9];
    const float* bn1_v    = (const float*)d_in[10];
    const float* conv2_w  = (const float*)d_in[11];
    const float* conv2_b  = (const float*)d_in[12];
    const float* bn2_g    = (const float*)d_in[13];
    const float* bn2_b    = (const float*)d_in[14];
    const float* bn2_m    = (const float*)d_in[15];
    const float* bn2_v    = (const float*)d_in[16];
    const float* logits_w = (const float*)d_in[17];
    const float* logits_b = (const float*)d_in[18];
    const float* bbox_w   = (const float*)d_in[19];
    const float* bbox_b   = (const float*)d_in[20];
    float* out = (float*)d_out;

    __nv_bfloat16 *a1, *b1, *a2, *b2;
    float *shbuf, *sc1, *sf1, *sc2, *sf2;
    cudaGetSymbolAddress((void**)&a1, g_A1);
    cudaGetSymbolAddress((void**)&b1, g_B1);
    cudaGetSymbolAddress((void**)&a2, g_A2);
    cudaGetSymbolAddress((void**)&b2, g_B2);
    cudaGetSymbolAddress((void**)&shbuf, g_sh);
    cudaGetSymbolAddress((void**)&sc1, g_scale1);
    cudaGetSymbolAddress((void**)&sf1, g_shift1);
    cudaGetSymbolAddress((void**)&sc2, g_scale2);
    cudaGetSymbolAddress((void**)&sf2, g_shift2);

    fuse_bn_kernel<<<8, 256>>>(conv1_b, bn1_g, bn1_b, bn1_m, bn1_v,
                               conv2_b, bn2_g, bn2_b, bn2_m, bn2_v);

    pool_kernel<<<N_ROIS, 256>>>(p2, p3, p4, p5, rois);

    convw_kernel<<<2048, 256>>>(conv1_w, b1, KDIM, (long)HID * KDIM);
    convw_kernel<<<512, 256>>>(conv2_w, b2, HID, (long)HID * HID);

    {
        dim3 grid(HID / 128, MPAD / 128);   // (8, 16)
        gemm_hmma_kernel<<<grid, 256>>>(a1, b1, K1P, sc1, sf1, nullptr, a2, 1);
        gemm_hmma_kernel<<<grid, 256>>>(a2, b2, K2P, sc2, sf2, shbuf, nullptr, 0);
    }

    head_kernel<<<N_ROIS, 128>>>(shbuf, logits_w, logits_b, bbox_w, bbox_b, out);
}

// round 5
// speedup vs baseline: 5.0270x; 1.4999x over previous
#include <cuda_runtime.h>
#include <cuda_bf16.h>
#include <math.h>
#include <stdint.h>

#define N_ROIS      2000
#define MPAD        2048
#define POOL        7
#define C_FEAT      256
#define KDIM        (C_FEAT * POOL * POOL)   // 12544
#define K1I         (2 * KDIM)               // 25088 interleaved
#define HID         1024
#define K2I         (2 * HID)                // 2048 interleaved
#define NUM_CLASSES 81
#define NBOX        (NUM_CLASSES * 4)        // 324
#define NHEAD       (NUM_CLASSES + NBOX)     // 405
#define NHEADP      512
#define BN_EPS      0.001f
#define IMG_DIM     1024.0f

// ---------------- scratch (device globals; zero-initialized) ---------------
__device__ __align__(128) __nv_bfloat16 g_A1[(size_t)MPAD * K1I];    // 103 MB
__device__ __align__(128) __nv_bfloat16 g_B1[(size_t)HID * K1I];     // 51 MB
__device__ __align__(128) __nv_bfloat16 g_A2[(size_t)MPAD * K2I];    // 8 MB
__device__ __align__(128) __nv_bfloat16 g_B2[(size_t)HID * K2I];     // 4 MB
__device__ __align__(128) __nv_bfloat16 g_A3[(size_t)MPAD * K2I];    // 8 MB
__device__ __align__(128) __nv_bfloat16 g_W3[(size_t)NHEADP * K2I];  // 2 MB
__device__ float g_scale1[HID], g_shift1[HID];
__device__ float g_scale2[HID], g_shift2[HID];
__device__ float g_shift3[NHEADP];

// ---------------- helpers ---------------------------------------------------
__device__ __forceinline__ uint32_t smem_u32(const void* p) {
    uint32_t a;
    asm("{ .reg .u64 t; cvta.to.shared.u64 t, %1; cvt.u32.u64 %0, t; }" : "=r"(a) : "l"(p));
    return a;
}
__device__ __forceinline__ void split_bf16(float v, __nv_bfloat16& h, __nv_bfloat16& l) {
    h = __float2bfloat16(v);
    l = __float2bfloat16(v - __bfloat162float(h));
}
__device__ __forceinline__ void cp16(uint32_t sa, const void* ga) {
    asm volatile("cp.async.cg.shared.global [%0], [%1], 16;" :: "r"(sa), "l"(ga));
}
__device__ __forceinline__ void cp_commit() {
    asm volatile("cp.async.commit_group;" ::: "memory");
}
__device__ __forceinline__ void cp_wait2() {
    asm volatile("cp.async.wait_group 2;" ::: "memory");
}
__device__ __forceinline__ void ldsm_x4(uint32_t& r0, uint32_t& r1, uint32_t& r2, uint32_t& r3,
                                        uint32_t addr) {
    asm volatile("ldmatrix.sync.aligned.m8n8.x4.shared.b16 {%0,%1,%2,%3}, [%4];"
                 : "=r"(r0), "=r"(r1), "=r"(r2), "=r"(r3) : "r"(addr));
}
__device__ __forceinline__ void mma_bf16(float* d, const uint32_t* a, const uint32_t* b) {
    asm volatile(
        "mma.sync.aligned.m16n8k16.row.col.f32.bf16.bf16.f32 "
        "{%0,%1,%2,%3}, {%4,%5,%6,%7}, {%8,%9}, {%0,%1,%2,%3};"
        : "+f"(d[0]), "+f"(d[1]), "+f"(d[2]), "+f"(d[3])
        : "r"(a[0]), "r"(a[1]), "r"(a[2]), "r"(a[3]), "r"(b[0]), "r"(b[1]));
}
// interleaved offset: element k of a row maps to block(k/16)*32 + k%16 (hi), +16 (lo)
__device__ __forceinline__ int ioff(int k) { return ((k >> 4) << 5) + (k & 15); }

// ---------------- fold BN (+bias) into scale/shift; build head bias --------
__global__ void fuse_bn_kernel(const float* __restrict__ cb1, const float* __restrict__ g1,
                               const float* __restrict__ b1, const float* __restrict__ m1,
                               const float* __restrict__ v1,
                               const float* __restrict__ cb2, const float* __restrict__ g2,
                               const float* __restrict__ b2, const float* __restrict__ m2,
                               const float* __restrict__ v2,
                               const float* __restrict__ lb, const float* __restrict__ bb)
{
    int i = blockIdx.x * blockDim.x + threadIdx.x;
    if (i < HID) {
        float s = g1[i] * rsqrtf(v1[i] + BN_EPS);
        g_scale1[i] = s;
        g_shift1[i] = (cb1[i] - m1[i]) * s + b1[i];
    } else if (i < 2 * HID) {
        int j = i - HID;
        float s = g2[j] * rsqrtf(v2[j] + BN_EPS);
        g_scale2[j] = s;
        g_shift2[j] = (cb2[j] - m2[j]) * s + b2[j];
    } else if (i < 2 * HID + NHEADP) {
        int j = i - 2 * HID;
        float v = 0.f;
        if (j < NUM_CLASSES)      v = lb[j];
        else if (j < NHEAD)       v = bb[j - NUM_CLASSES];
        g_shift3[j] = v;
    }
}

// ------- weight split: W[N,K] fp32 -> [N,2K] bf16 interleaved hi/lo --------
__global__ void convw_kernel(const float* __restrict__ W, __nv_bfloat16* __restrict__ out,
                             int K, long total)
{
    long idx = (long)blockIdx.x * blockDim.x + threadIdx.x;
    long stride = (long)gridDim.x * blockDim.x;
    for (; idx < total; idx += stride) {
        int n = (int)(idx / K);
        int k = (int)(idx % K);
        __nv_bfloat16 h, l;
        split_bf16(W[idx], h, l);
        __nv_bfloat16* row = out + (size_t)n * (2 * K);
        int o = ioff(k);
        row[o] = h;
        row[o + 16] = l;
    }
}

// ---------------- ROI-Align pooling -> bf16 interleaved A1 -----------------
__global__ void pool_kernel(const float* __restrict__ p2, const float* __restrict__ p3,
                            const float* __restrict__ p4, const float* __restrict__ p5,
                            const float* __restrict__ rois)
{
    int n = blockIdx.x;
    int tid = threadIdx.x;

    float x1 = rois[4 * n + 0];
    float y1 = rois[4 * n + 1];
    float x2 = rois[4 * n + 2];
    float y2 = rois[4 * n + 3];

    float area = (y2 - y1) * (x2 - x1);
    float lv = rintf(log2f(sqrtf(area) / 224.0f)) + 4.0f;
    lv = fminf(fmaxf(lv, 2.0f), 5.0f);
    int lvl = (int)lv;

    const float* fmap;
    int H;
    if (lvl == 2)      { fmap = p2; H = 256; }
    else if (lvl == 3) { fmap = p3; H = 128; }
    else if (lvl == 4) { fmap = p4; H = 64;  }
    else               { fmap = p5; H = 32;  }

    float ny1 = y1 / IMG_DIM, nx1 = x1 / IMG_DIM;
    float ny2 = y2 / IMG_DIM, nx2 = x2 / IMG_DIM;

    __shared__ float s_ly[POOL], s_lx[POOL];
    __shared__ int   s_y0[POOL], s_y1[POOL], s_x0[POOL], s_x1[POOL];

    if (tid < POOL) {
        int i = tid;
        float t = (float)i / (float)(POOL - 1);
        float Hm1 = (float)(H - 1);
        float ys = ny1 * Hm1 + t * ((ny2 - ny1) * Hm1);
        float y0 = floorf(ys);
        s_ly[i] = ys - y0;
        int y0i = min(max((int)y0, 0), H - 1);
        s_y0[i] = y0i;
        s_y1[i] = min(y0i + 1, H - 1);
    } else if (tid < 2 * POOL) {
        int i = tid - POOL;
        float t = (float)i / (float)(POOL - 1);
        float Wm1 = (float)(H - 1);
        float xs = nx1 * Wm1 + t * ((nx2 - nx1) * Wm1);
        float x0 = floorf(xs);
        s_lx[i] = xs - x0;
        int x0i = min(max((int)x0, 0), H - 1);
        s_x0[i] = x0i;
        s_x1[i] = min(x0i + 1, H - 1);
    }
    __syncthreads();

    int HW = H * H;
    __nv_bfloat16* arow = g_A1 + (size_t)n * K1I;

    for (int idx = tid; idx < KDIM; idx += blockDim.x) {
        int c  = idx / (POOL * POOL);
        int p  = idx % (POOL * POOL);
        int iy = p / POOL;
        int ix = p % POOL;
        const float* f = fmap + (size_t)c * HW;
        int y0 = s_y0[iy], y1i = s_y1[iy];
        int x0 = s_x0[ix], x1i = s_x1[ix];
        float fy = s_ly[iy], fx = s_lx[ix];
        float v00 = f[y0  * H + x0 ];
        float v01 = f[y0  * H + x1i];
        float v10 = f[y1i * H + x0 ];
        float v11 = f[y1i * H + x1i];
        float v = v00 * (1.f - fy) * (1.f - fx)
                + v01 * (1.f - fy) * fx
                + v10 * fy * (1.f - fx)
                + v11 * fy * fx;
        __nv_bfloat16 h, l;
        split_bf16(v, h, l);
        int o = ioff(idx);
        arow[o] = h;
        arow[o + 16] = l;
    }
}

// ---------------- HMMA bf16 GEMM over interleaved hi/lo operands -----------
// Per 32-wide chunk (16 logical k): passes (Ah,Bh) + (Al,Bh) + (Ah,Bl).
#define KSTEP       32
#define STAGES      3
#define TILE_BYTES  16384
#define ROW_BYTES   64

__device__ __forceinline__ uint32_t sw_off(int row, int ch) {
    return (uint32_t)(row * ROW_BYTES + ((ch ^ ((row >> 1) & 3)) << 4));
}

__device__ __forceinline__ void load_tile(uint32_t sbase, const __nv_bfloat16* g,
                                          int row0, int ldK, int k0, int tid)
{
#pragma unroll
    for (int j = 0; j < 2; j++) {
        int u = tid + j * 256;
        int row = u >> 2;
        int ch = u & 3;
        cp16(sbase + sw_off(row, ch),
             (const void*)(g + (size_t)(row0 + row) * ldK + k0 + ch * 8));
    }
}

// mode 1: Cb += interleaved bf16 out (relu((x*scale)+shift)), row len 2048
// mode 2: head writer -> logits/bbox into d_out (x + shift, no relu)
__global__ __launch_bounds__(256)
void gemm_hmma_kernel(const __nv_bfloat16* __restrict__ A, const __nv_bfloat16* __restrict__ B,
                      int Kp,
                      const float* __restrict__ scale, const float* __restrict__ shift,
                      float* __restrict__ Cf, __nv_bfloat16* __restrict__ Cb, int mode)
{
    __shared__ __align__(1024) uint8_t smem[STAGES * TILE_BYTES];

    int tid = threadIdx.x;
    int wid = tid >> 5;
    int lane = tid & 31;
    int wm = wid & 3;
    int wn = wid >> 2;
    int m0 = blockIdx.y * 128;
    int n0 = blockIdx.x * 128;

    uint32_t sb = smem_u32(smem);

    float acc[2][8][4];
#pragma unroll
    for (int i = 0; i < 2; i++)
#pragma unroll
        for (int j = 0; j < 8; j++)
#pragma unroll
            for (int q = 0; q < 4; q++) acc[i][j][q] = 0.f;

    int nk = Kp / KSTEP;

#pragma unroll
    for (int s = 0; s < STAGES; s++) {
        load_tile(sb + s * TILE_BYTES,        A, m0, Kp, s * KSTEP, tid);
        load_tile(sb + s * TILE_BYTES + 8192, B, n0, Kp, s * KSTEP, tid);
        cp_commit();
    }

    int arow = wm * 32 + (lane & 15);
    int ach  = lane >> 4;                    // chunk 0/1 = hi, +2 = lo
    int brow = wn * 64 + (lane & 7) + ((lane & 16) ? 8 : 0);
    int bch  = (lane & 8) ? 1 : 0;

    for (int i = 0; i < nk; i++) {
        cp_wait2();
        __syncthreads();
        uint32_t st = sb + (uint32_t)(i % STAGES) * TILE_BYTES;

        uint32_t ah[2][4], al[2][4], bh[8][2], bl[8][2];
#pragma unroll
        for (int mi = 0; mi < 2; mi++) {
            ldsm_x4(ah[mi][0], ah[mi][1], ah[mi][2], ah[mi][3],
                    st + sw_off(arow + mi * 16, ach));
            ldsm_x4(al[mi][0], al[mi][1], al[mi][2], al[mi][3],
                    st + sw_off(arow + mi * 16, ach + 2));
        }
#pragma unroll
        for (int nt = 0; nt < 4; nt++) {
            ldsm_x4(bh[nt * 2][0], bh[nt * 2][1], bh[nt * 2 + 1][0], bh[nt * 2 + 1][1],
                    st + 8192 + sw_off(brow + nt * 16, bch));
            ldsm_x4(bl[nt * 2][0], bl[nt * 2][1], bl[nt * 2 + 1][0], bl[nt * 2 + 1][1],
                    st + 8192 + sw_off(brow + nt * 16, bch + 2));
        }
#pragma unroll
        for (int mi = 0; mi < 2; mi++)
#pragma unroll
            for (int nj = 0; nj < 8; nj++)
                mma_bf16(acc[mi][nj], ah[mi], bh[nj]);
#pragma unroll
        for (int mi = 0; mi < 2; mi++)
#pragma unroll
            for (int nj = 0; nj < 8; nj++)
                mma_bf16(acc[mi][nj], al[mi], bh[nj]);
#pragma unroll
        for (int mi = 0; mi < 2; mi++)
#pragma unroll
            for (int nj = 0; nj < 8; nj++)
                mma_bf16(acc[mi][nj], ah[mi], bl[nj]);

        __syncthreads();
        int j = i + STAGES;
        if (j < nk) {
            load_tile(st,        A, m0, Kp, j * KSTEP, tid);
            load_tile(st + 8192, B, n0, Kp, j * KSTEP, tid);
        }
        cp_commit();
    }

#pragma unroll
    for (int mi = 0; mi < 2; mi++) {
        int rbase = m0 + wm * 32 + mi * 16 + (lane >> 2);
#pragma unroll
        for (int nj = 0; nj < 8; nj++) {
            int c = n0 + wn * 64 + nj * 8 + (lane & 3) * 2;
#pragma unroll
            for (int half = 0; half < 2; half++) {
                int m = rbase + half * 8;
                if (m >= N_ROIS) continue;
                if (mode == 1) {
                    float v0 = fmaxf(acc[mi][nj][half * 2 + 0] * scale[c]     + shift[c],     0.f);
                    float v1 = fmaxf(acc[mi][nj][half * 2 + 1] * scale[c + 1] + shift[c + 1], 0.f);
                    __nv_bfloat16 h0, l0, h1, l1;
                    split_bf16(v0, h0, l0);
                    split_bf16(v1, h1, l1);
                    __nv_bfloat162 hh; hh.x = h0; hh.y = h1;
                    __nv_bfloat162 ll; ll.x = l0; ll.y = l1;
                    __nv_bfloat16* crow = Cb + (size_t)m * K2I + ioff(c);
                    *reinterpret_cast<__nv_bfloat162*>(&crow[0])  = hh;
                    *reinterpret_cast<__nv_bfloat162*>(&crow[16]) = ll;
                } else {
#pragma unroll
                    for (int e = 0; e < 2; e++) {
                        int col = c + e;
                        if (col >= NHEAD) continue;
                        float v = acc[mi][nj][half * 2 + e] + shift[col];
                        if (col < NUM_CLASSES)
                            Cf[(size_t)m * NUM_CLASSES + col] = v;
                        else
                            Cf[(size_t)(2 * N_ROIS * NUM_CLASSES) +
                               (size_t)m * NBOX + (col - NUM_CLASSES)] = v;
                    }
                }
            }
        }
    }
}

// ---------------- softmax over logits -> probs -----------------------------
__global__ __launch_bounds__(128)
void softmax_kernel(float* __restrict__ out)
{
    int roi = blockIdx.x * 4 + (threadIdx.x >> 5);
    int lane = threadIdx.x & 31;
    if (roi >= N_ROIS) return;
    const float* lg = out + (size_t)roi * NUM_CLASSES;
    float* pr = out + (size_t)N_ROIS * NUM_CLASSES + (size_t)roi * NUM_CLASSES;

    float mx = -INFINITY;
    for (int k = lane; k < NUM_CLASSES; k += 32) mx = fmaxf(mx, lg[k]);
#pragma unroll
    for (int off = 16; off > 0; off >>= 1)
        mx = fmaxf(mx, __shfl_xor_sync(0xFFFFFFFFu, mx, off));

    float s = 0.f;
    for (int k = lane; k < NUM_CLASSES; k += 32) s += expf(lg[k] - mx);
#pragma unroll
    for (int off = 16; off > 0; off >>= 1)
        s += __shfl_xor_sync(0xFFFFFFFFu, s, off);

    float inv = 1.f / s;
    for (int k = lane; k < NUM_CLASSES; k += 32)
        pr[k] = expf(lg[k] - mx) * inv;
}

// ---------------- launch ---------------------------------------------------
extern "C" void kernel_launch(void* const* d_in, const int* in_sizes, int n_in,
                              void* d_out, int out_size)
{
    const float* p2       = (const float*)d_in[0];
    const float* p3       = (const float*)d_in[1];
    const float* p4       = (const float*)d_in[2];
    const float* p5       = (const float*)d_in[3];
    const float* rois     = (const float*)d_in[4];
    const float* conv1_w  = (const float*)d_in[5];
    const float* conv1_b  = (const float*)d_in[6];
    const float* bn1_g    = (const float*)d_in[7];
    const float* bn1_b    = (const float*)d_in[8];
    const float* bn1_m    = (const float*)d_in[9];
    const float* bn1_v    = (const float*)d_in[10];
    const float* conv2_w  = (const float*)d_in[11];
    const float* conv2_b  = (const float*)d_in[12];
    const float* bn2_g    = (const float*)d_in[13];
    const float* bn2_b    = (const float*)d_in[14];
    const float* bn2_m    = (const float*)d_in[15];
    const float* bn2_v    = (const float*)d_in[16];
    const float* logits_w = (const float*)d_in[17];
    const float* logits_b = (const float*)d_in[18];
    const float* bbox_w   = (const float*)d_in[19];
    const float* bbox_b   = (const float*)d_in[20];
    float* out = (float*)d_out;

    __nv_bfloat16 *a1, *b1, *a2, *b2, *a3, *w3;
    float *sc1, *sf1, *sc2, *sf2, *sf3;
    cudaGetSymbolAddress((void**)&a1, g_A1);
    cudaGetSymbolAddress((void**)&b1, g_B1);
    cudaGetSymbolAddress((void**)&a2, g_A2);
    cudaGetSymbolAddress((void**)&b2, g_B2);
    cudaGetSymbolAddress((void**)&a3, g_A3);
    cudaGetSymbolAddress((void**)&w3, g_W3);
    cudaGetSymbolAddress((void**)&sc1, g_scale1);
    cudaGetSymbolAddress((void**)&sf1, g_shift1);
    cudaGetSymbolAddress((void**)&sc2, g_scale2);
    cudaGetSymbolAddress((void**)&sf2, g_shift2);
    cudaGetSymbolAddress((void**)&sf3, g_shift3);

    fuse_bn_kernel<<<10, 256>>>(conv1_b, bn1_g, bn1_b, bn1_m, bn1_v,
                                conv2_b, bn2_g, bn2_b, bn2_m, bn2_v,
                                logits_b, bbox_b);

    pool_kernel<<<N_ROIS, 256>>>(p2, p3, p4, p5, rois);

    convw_kernel<<<2048, 256>>>(conv1_w, b1, KDIM, (long)HID * KDIM);
    convw_kernel<<<512, 256>>>(conv2_w, b2, HID, (long)HID * HID);
    convw_kernel<<<128, 256>>>(logits_w, w3, HID, (long)NUM_CLASSES * HID);
    convw_kernel<<<256, 256>>>(bbox_w, w3 + (size_t)NUM_CLASSES * K2I, HID,
                               (long)NBOX * HID);

    {
        dim3 grid1(HID / 128, MPAD / 128);     // (8, 16)
        gemm_hmma_kernel<<<grid1, 256>>>(a1, b1, K1I, sc1, sf1, nullptr, a2, 1);
        gemm_hmma_kernel<<<grid1, 256>>>(a2, b2, K2I, sc2, sf2, nullptr, a3, 1);
        dim3 grid3(NHEADP / 128, MPAD / 128);  // (4, 16)
        gemm_hmma_kernel<<<grid3, 256>>>(a3, w3, K2I, nullptr, sf3, out, nullptr, 2);
    }

    softmax_kernel<<<(N_ROIS + 3) / 4, 128>>>(out);
}

// round 6
// speedup vs baseline: 5.1580x; 1.0261x over previous
#include <cuda_runtime.h>
#include <cuda_bf16.h>
#include <math.h>
#include <stdint.h>

#define N_ROIS      2000
#define MPAD        2048
#define POOL        7
#define C_FEAT      256
#define KDIM        (C_FEAT * POOL * POOL)   // 12544
#define K1I         (2 * KDIM)               // 25088 interleaved
#define HID         1024
#define K2I         (2 * HID)                // 2048 interleaved
#define NUM_CLASSES 81
#define NBOX        (NUM_CLASSES * 4)        // 324
#define NHEAD       (NUM_CLASSES + NBOX)     // 405
#define NHEADP      512
#define BN_EPS      0.001f
#define IMG_DIM     1024.0f

// prep kernel block layout
#define PB_POOL     N_ROIS                  // [0, 2000)
#define NB_CW1      256
#define NB_CW2      32
#define NB_CW3      16
#define NB_BN       10
#define PB_CW1      (PB_POOL)               // +NB_CW1
#define PB_CW2      (PB_CW1 + NB_CW1)
#define PB_CW3      (PB_CW2 + NB_CW2)
#define PB_BN       (PB_CW3 + NB_CW3)
#define PREP_GRID   (PB_BN + NB_BN)

// ---------------- scratch (device globals; zero-initialized) ---------------
__device__ __align__(128) __nv_bfloat16 g_A1[(size_t)MPAD * K1I];
__device__ __align__(128) __nv_bfloat16 g_B1[(size_t)HID * K1I];
__device__ __align__(128) __nv_bfloat16 g_A2[(size_t)MPAD * K2I];
__device__ __align__(128) __nv_bfloat16 g_B2[(size_t)HID * K2I];
__device__ __align__(128) __nv_bfloat16 g_A3[(size_t)MPAD * K2I];
__device__ __align__(128) __nv_bfloat16 g_W3[(size_t)NHEADP * K2I];
__device__ float g_scale1[HID], g_shift1[HID];
__device__ float g_scale2[HID], g_shift2[HID];
__device__ float g_shift3[NHEADP];

// ---------------- helpers ---------------------------------------------------
__device__ __forceinline__ uint32_t smem_u32(const void* p) {
    uint32_t a;
    asm("{ .reg .u64 t; cvta.to.shared.u64 t, %1; cvt.u32.u64 %0, t; }" : "=r"(a) : "l"(p));
    return a;
}
__device__ __forceinline__ void split_bf16(float v, __nv_bfloat16& h, __nv_bfloat16& l) {
    h = __float2bfloat16(v);
    l = __float2bfloat16(v - __bfloat162float(h));
}
__device__ __forceinline__ void cp16(uint32_t sa, const void* ga) {
    asm volatile("cp.async.cg.shared.global [%0], [%1], 16;" :: "r"(sa), "l"(ga));
}
__device__ __forceinline__ void cp_commit() {
    asm volatile("cp.async.commit_group;" ::: "memory");
}
__device__ __forceinline__ void cp_wait2() {
    asm volatile("cp.async.wait_group 2;" ::: "memory");
}
__device__ __forceinline__ void ldsm_x4(uint32_t& r0, uint32_t& r1, uint32_t& r2, uint32_t& r3,
                                        uint32_t addr) {
    asm volatile("ldmatrix.sync.aligned.m8n8.x4.shared.b16 {%0,%1,%2,%3}, [%4];"
                 : "=r"(r0), "=r"(r1), "=r"(r2), "=r"(r3) : "r"(addr));
}
__device__ __forceinline__ void mma_bf16(float* d, const uint32_t* a, const uint32_t* b) {
    asm volatile(
        "mma.sync.aligned.m16n8k16.row.col.f32.bf16.bf16.f32 "
        "{%0,%1,%2,%3}, {%4,%5,%6,%7}, {%8,%9}, {%0,%1,%2,%3};"
        : "+f"(d[0]), "+f"(d[1]), "+f"(d[2]), "+f"(d[3])
        : "r"(a[0]), "r"(a[1]), "r"(a[2]), "r"(a[3]), "r"(b[0]), "r"(b[1]));
}
__device__ __forceinline__ int ioff(int k) { return ((k >> 4) << 5) + (k & 15); }

// ---- vectorized weight split: one unit = 16 consecutive k of one row ------
__device__ __forceinline__ void convw_unit(const float* __restrict__ W,
                                           __nv_bfloat16* __restrict__ out,
                                           int K, long u)
{
    int kb16 = K >> 4;
    int n = (int)(u / kb16);
    int kb = (int)(u % kb16);
    const float4* src = reinterpret_cast<const float4*>(W + (size_t)n * K + (size_t)kb * 16);
    float w[16];
#pragma unroll
    for (int q = 0; q < 4; q++) {
        float4 f = src[q];
        w[q * 4 + 0] = f.x; w[q * 4 + 1] = f.y; w[q * 4 + 2] = f.z; w[q * 4 + 3] = f.w;
    }
    __nv_bfloat16 h[16], l[16];
#pragma unroll
    for (int j = 0; j < 16; j++) split_bf16(w[j], h[j], l[j]);
    __nv_bfloat16* dst = out + (size_t)n * (2 * K) + (size_t)kb * 32;
    uint4* d4 = reinterpret_cast<uint4*>(dst);
    d4[0] = *reinterpret_cast<uint4*>(&h[0]);
    d4[1] = *reinterpret_cast<uint4*>(&h[8]);
    d4[2] = *reinterpret_cast<uint4*>(&l[0]);
    d4[3] = *reinterpret_cast<uint4*>(&l[8]);
}

// ---------------- mega prep: pool + convw splits + bn fold -----------------
__global__ __launch_bounds__(256)
void prep_kernel(const float* __restrict__ p2, const float* __restrict__ p3,
                 const float* __restrict__ p4, const float* __restrict__ p5,
                 const float* __restrict__ rois,
                 const float* __restrict__ conv1_w, const float* __restrict__ conv2_w,
                 const float* __restrict__ logits_w, const float* __restrict__ bbox_w,
                 const float* __restrict__ cb1, const float* __restrict__ g1,
                 const float* __restrict__ b1, const float* __restrict__ m1,
                 const float* __restrict__ v1,
                 const float* __restrict__ cb2, const float* __restrict__ g2,
                 const float* __restrict__ b2, const float* __restrict__ m2,
                 const float* __restrict__ v2,
                 const float* __restrict__ lb, const float* __restrict__ bb)
{
    int bid = blockIdx.x;
    int tid = threadIdx.x;

    if (bid < PB_POOL) {
        // ---------------- ROI-Align pooling -> interleaved A1 --------------
        int n = bid;
        float x1 = rois[4 * n + 0];
        float y1 = rois[4 * n + 1];
        float x2 = rois[4 * n + 2];
        float y2 = rois[4 * n + 3];

        float area = (y2 - y1) * (x2 - x1);
        float lv = rintf(log2f(sqrtf(area) / 224.0f)) + 4.0f;
        lv = fminf(fmaxf(lv, 2.0f), 5.0f);
        int lvl = (int)lv;

        const float* fmap;
        int H;
        if (lvl == 2)      { fmap = p2; H = 256; }
        else if (lvl == 3) { fmap = p3; H = 128; }
        else if (lvl == 4) { fmap = p4; H = 64;  }
        else               { fmap = p5; H = 32;  }

        float ny1 = y1 / IMG_DIM, nx1 = x1 / IMG_DIM;
        float ny2 = y2 / IMG_DIM, nx2 = x2 / IMG_DIM;

        __shared__ float s_ly[POOL], s_lx[POOL];
        __shared__ int   s_y0[POOL], s_y1[POOL], s_x0[POOL], s_x1[POOL];

        if (tid < POOL) {
            int i = tid;
            float t = (float)i / (float)(POOL - 1);
            float Hm1 = (float)(H - 1);
            float ys = ny1 * Hm1 + t * ((ny2 - ny1) * Hm1);
            float y0 = floorf(ys);
            s_ly[i] = ys - y0;
            int y0i = min(max((int)y0, 0), H - 1);
            s_y0[i] = y0i;
            s_y1[i] = min(y0i + 1, H - 1);
        } else if (tid < 2 * POOL) {
            int i = tid - POOL;
            float t = (float)i / (float)(POOL - 1);
            float Wm1 = (float)(H - 1);
            float xs = nx1 * Wm1 + t * ((nx2 - nx1) * Wm1);
            float x0 = floorf(xs);
            s_lx[i] = xs - x0;
            int x0i = min(max((int)x0, 0), H - 1);
            s_x0[i] = x0i;
            s_x1[i] = min(x0i + 1, H - 1);
        }
        __syncthreads();

        int HW = H * H;
        __nv_bfloat16* arow = g_A1 + (size_t)n * K1I;

        for (int base = tid * 2; base < KDIM; base += 512) {
            __nv_bfloat16 hh[2], ll[2];
#pragma unroll
            for (int e = 0; e < 2; e++) {
                int idx = base + e;
                int c  = idx / (POOL * POOL);
                int p  = idx % (POOL * POOL);
                int iy = p / POOL;
                int ix = p % POOL;
                const float* f = fmap + (size_t)c * HW;
                int y0 = s_y0[iy], y1i = s_y1[iy];
                int x0 = s_x0[ix], x1i = s_x1[ix];
                float fy = s_ly[iy], fx = s_lx[ix];
                float v00 = __ldg(&f[y0  * H + x0 ]);
                float v01 = __ldg(&f[y0  * H + x1i]);
                float v10 = __ldg(&f[y1i * H + x0 ]);
                float v11 = __ldg(&f[y1i * H + x1i]);
                float v = v00 * (1.f - fy) * (1.f - fx)
                        + v01 * (1.f - fy) * fx
                        + v10 * fy * (1.f - fx)
                        + v11 * fy * fx;
                split_bf16(v, hh[e], ll[e]);
            }
            // base is even -> base%16 != 15 -> both elems in same 16-block
            int o = ioff(base);
            __nv_bfloat162 hp; hp.x = hh[0]; hp.y = hh[1];
            __nv_bfloat162 lp; lp.x = ll[0]; lp.y = ll[1];
            *reinterpret_cast<__nv_bfloat162*>(&arow[o])      = hp;
            *reinterpret_cast<__nv_bfloat162*>(&arow[o + 16]) = lp;
        }
    } else if (bid < PB_CW2) {
        // convw conv1: 1024 x 12544
        long units = (long)HID * (KDIM >> 4);
        long start = (long)(bid - PB_CW1) * 256 + tid;
        long stride = (long)NB_CW1 * 256;
        for (long u = start; u < units; u += stride)
            convw_unit(conv1_w, g_B1, KDIM, u);
    } else if (bid < PB_CW3) {
        // convw conv2: 1024 x 1024
        long units = (long)HID * (HID >> 4);
        long start = (long)(bid - PB_CW2) * 256 + tid;
        long stride = (long)NB_CW2 * 256;
        for (long u = start; u < units; u += stride)
            convw_unit(conv2_w, g_B2, HID, u);
    } else if (bid < PB_BN) {
        // convw head: 405 rows of 1024 into g_W3
        long units = (long)NHEAD * (HID >> 4);
        long start = (long)(bid - PB_CW3) * 256 + tid;
        long stride = (long)NB_CW3 * 256;
        int kb16 = HID >> 4;
        for (long u = start; u < units; u += stride) {
            int r = (int)(u / kb16);
            long uu = u % kb16;
            if (r < NUM_CLASSES)
                convw_unit(logits_w, g_W3, HID, (long)r * kb16 + uu);
            else
                convw_unit(bbox_w, g_W3 + (size_t)NUM_CLASSES * K2I, HID,
                           (long)(r - NUM_CLASSES) * kb16 + uu);
        }
    } else {
        // bn fold + head bias
        int i = (bid - PB_BN) * 256 + tid;
        if (i < HID) {
            float s = g1[i] * rsqrtf(v1[i] + BN_EPS);
            g_scale1[i] = s;
            g_shift1[i] = (cb1[i] - m1[i]) * s + b1[i];
        } else if (i < 2 * HID) {
            int j = i - HID;
            float s = g2[j] * rsqrtf(v2[j] + BN_EPS);
            g_scale2[j] = s;
            g_shift2[j] = (cb2[j] - m2[j]) * s + b2[j];
        } else if (i < 2 * HID + NHEADP) {
            int j = i - 2 * HID;
            float v = 0.f;
            if (j < NUM_CLASSES)      v = lb[j];
            else if (j < NHEAD)       v = bb[j - NUM_CLASSES];
            g_shift3[j] = v;
        }
    }
}

// ---------------- HMMA bf16 GEMM over interleaved hi/lo operands -----------
#define KSTEP       32
#define STAGES      3
#define TILE_BYTES  16384
#define ROW_BYTES   64

__device__ __forceinline__ uint32_t sw_off(int row, int ch) {
    return (uint32_t)(row * ROW_BYTES + ((ch ^ ((row >> 1) & 3)) << 4));
}

__device__ __forceinline__ void load_tile(uint32_t sbase, const __nv_bfloat16* g,
                                          int row0, int ldK, int k0, int tid)
{
#pragma unroll
    for (int j = 0; j < 2; j++) {
        int u = tid + j * 256;
        int row = u >> 2;
        int ch = u & 3;
        cp16(sbase + sw_off(row, ch),
             (const void*)(g + (size_t)(row0 + row) * ldK + k0 + ch * 8));
    }
}

__global__ __launch_bounds__(256)
void gemm_hmma_kernel(const __nv_bfloat16* __restrict__ A, const __nv_bfloat16* __restrict__ B,
                      int Kp,
                      const float* __restrict__ scale, const float* __restrict__ shift,
                      float* __restrict__ Cf, __nv_bfloat16* __restrict__ Cb, int mode)
{
    __shared__ __align__(1024) uint8_t smem[STAGES * TILE_BYTES];

    int tid = threadIdx.x;
    int wid = tid >> 5;
    int lane = tid & 31;
    int wm = wid & 3;
    int wn = wid >> 2;
    int m0 = blockIdx.y * 128;
    int n0 = blockIdx.x * 128;

    uint32_t sb = smem_u32(smem);

    float acc[2][8][4];
#pragma unroll
    for (int i = 0; i < 2; i++)
#pragma unroll
        for (int j = 0; j < 8; j++)
#pragma unroll
            for (int q = 0; q < 4; q++) acc[i][j][q] = 0.f;

    int nk = Kp / KSTEP;

#pragma unroll
    for (int s = 0; s < STAGES; s++) {
        load_tile(sb + s * TILE_BYTES,        A, m0, Kp, s * KSTEP, tid);
        load_tile(sb + s * TILE_BYTES + 8192, B, n0, Kp, s * KSTEP, tid);
        cp_commit();
    }

    int arow = wm * 32 + (lane & 15);
    int ach  = lane >> 4;
    int brow = wn * 64 + (lane & 7) + ((lane & 16) ? 8 : 0);
    int bch  = (lane & 8) ? 1 : 0;

    for (int i = 0; i < nk; i++) {
        cp_wait2();
        __syncthreads();
        uint32_t st = sb + (uint32_t)(i % STAGES) * TILE_BYTES;

        uint32_t ah[2][4], al[2][4], bh[8][2], bl[8][2];
#pragma unroll
        for (int mi = 0; mi < 2; mi++) {
            ldsm_x4(ah[mi][0], ah[mi][1], ah[mi][2], ah[mi][3],
                    st + sw_off(arow + mi * 16, ach));
            ldsm_x4(al[mi][0], al[mi][1], al[mi][2], al[mi][3],
                    st + sw_off(arow + mi * 16, ach + 2));
        }
#pragma unroll
        for (int nt = 0; nt < 4; nt++) {
            ldsm_x4(bh[nt * 2][0], bh[nt * 2][1], bh[nt * 2 + 1][0], bh[nt * 2 + 1][1],
                    st + 8192 + sw_off(brow + nt * 16, bch));
            ldsm_x4(bl[nt * 2][0], bl[nt * 2][1], bl[nt * 2 + 1][0], bl[nt * 2 + 1][1],
                    st + 8192 + sw_off(brow + nt * 16, bch + 2));
        }
#pragma unroll
        for (int mi = 0; mi < 2; mi++)
#pragma unroll
            for (int nj = 0; nj < 8; nj++)
                mma_bf16(acc[mi][nj], ah[mi], bh[nj]);
#pragma unroll
        for (int mi = 0; mi < 2; mi++)
#pragma unroll
            for (int nj = 0; nj < 8; nj++)
                mma_bf16(acc[mi][nj], al[mi], bh[nj]);
#pragma unroll
        for (int mi = 0; mi < 2; mi++)
#pragma unroll
            for (int nj = 0; nj < 8; nj++)
                mma_bf16(acc[mi][nj], ah[mi], bl[nj]);

        __syncthreads();
        int j = i + STAGES;
        if (j < nk) {
            load_tile(st,        A, m0, Kp, j * KSTEP, tid);
            load_tile(st + 8192, B, n0, Kp, j * KSTEP, tid);
        }
        cp_commit();
    }

#pragma unroll
    for (int mi = 0; mi < 2; mi++) {
        int rbase = m0 + wm * 32 + mi * 16 + (lane >> 2);
#pragma unroll
        for (int nj = 0; nj < 8; nj++) {
            int c = n0 + wn * 64 + nj * 8 + (lane & 3) * 2;
#pragma unroll
            for (int half = 0; half < 2; half++) {
                int m = rbase + half * 8;
                if (m >= N_ROIS) continue;
                if (mode == 1) {
                    float v0 = fmaxf(acc[mi][nj][half * 2 + 0] * scale[c]     + shift[c],     0.f);
                    float v1 = fmaxf(acc[mi][nj][half * 2 + 1] * scale[c + 1] + shift[c + 1], 0.f);
                    __nv_bfloat16 h0, l0, h1, l1;
                    split_bf16(v0, h0, l0);
                    split_bf16(v1, h1, l1);
                    __nv_bfloat162 hh; hh.x = h0; hh.y = h1;
                    __nv_bfloat162 ll; ll.x = l0; ll.y = l1;
                    __nv_bfloat16* crow = Cb + (size_t)m * K2I + ioff(c);
                    *reinterpret_cast<__nv_bfloat162*>(&crow[0])  = hh;
                    *reinterpret_cast<__nv_bfloat162*>(&crow[16]) = ll;
                } else {
#pragma unroll
                    for (int e = 0; e < 2; e++) {
                        int col = c + e;
                        if (col >= NHEAD) continue;
                        float v = acc[mi][nj][half * 2 + e] + shift[col];
                        if (col < NUM_CLASSES)
                            Cf[(size_t)m * NUM_CLASSES + col] = v;
                        else
                            Cf[(size_t)(2 * N_ROIS * NUM_CLASSES) +
                               (size_t)m * NBOX + (col - NUM_CLASSES)] = v;
                    }
                }
            }
        }
    }
}

// ---------------- softmax over logits -> probs -----------------------------
__global__ __launch_bounds__(128)
void softmax_kernel(float* __restrict__ out)
{
    int roi = blockIdx.x * 4 + (threadIdx.x >> 5);
    int lane = threadIdx.x & 31;
    if (roi >= N_ROIS) return;
    const float* lg = out + (size_t)roi * NUM_CLASSES;
    float* pr = out + (size_t)N_ROIS * NUM_CLASSES + (size_t)roi * NUM_CLASSES;

    float mx = -INFINITY;
    for (int k = lane; k < NUM_CLASSES; k += 32) mx = fmaxf(mx, lg[k]);
#pragma unroll
    for (int off = 16; off > 0; off >>= 1)
        mx = fmaxf(mx, __shfl_xor_sync(0xFFFFFFFFu, mx, off));

    float s = 0.f;
    for (int k = lane; k < NUM_CLASSES; k += 32) s += expf(lg[k] - mx);
#pragma unroll
    for (int off = 16; off > 0; off >>= 1)
        s += __shfl_xor_sync(0xFFFFFFFFu, s, off);

    float inv = 1.f / s;
    for (int k = lane; k < NUM_CLASSES; k += 32)
        pr[k] = expf(lg[k] - mx) * inv;
}

// ---------------- launch ---------------------------------------------------
extern "C" void kernel_launch(void* const* d_in, const int* in_sizes, int n_in,
                              void* d_out, int out_size)
{
    const float* p2       = (const float*)d_in[0];
    const float* p3       = (const float*)d_in[1];
    const float* p4       = (const float*)d_in[2];
    const float* p5       = (const float*)d_in[3];
    const float* rois     = (const float*)d_in[4];
    const float* conv1_w  = (const float*)d_in[5];
    const float* conv1_b  = (const float*)d_in[6];
    const float* bn1_g    = (const float*)d_in[7];
    const float* bn1_b    = (const float*)d_in[8];
    const float* bn1_m    = (const float*)d_in[9];
    const float* bn1_v    = (const float*)d_in[10];
    const float* conv2_w  = (const float*)d_in[11];
    const float* conv2_b  = (const float*)d_in[12];
    const float* bn2_g    = (const float*)d_in[13];
    const float* bn2_b    = (const float*)d_in[14];
    const float* bn2_m    = (const float*)d_in[15];
    const float* bn2_v    = (const float*)d_in[16];
    const float* logits_w = (const float*)d_in[17];
    const float* logits_b = (const float*)d_in[18];
    const float* bbox_w   = (const float*)d_in[19];
    const float* bbox_b   = (const float*)d_in[20];
    float* out = (float*)d_out;

    __nv_bfloat16 *a1, *b1, *a2, *b2, *a3, *w3;
    float *sc1, *sf1, *sc2, *sf2, *sf3;
    cudaGetSymbolAddress((void**)&a1, g_A1);
    cudaGetSymbolAddress((void**)&b1, g_B1);
    cudaGetSymbolAddress((void**)&a2, g_A2);
    cudaGetSymbolAddress((void**)&b2, g_B2);
    cudaGetSymbolAddress((void**)&a3, g_A3);
    cudaGetSymbolAddress((void**)&w3, g_W3);
    cudaGetSymbolAddress((void**)&sc1, g_scale1);
    cudaGetSymbolAddress((void**)&sf1, g_shift1);
    cudaGetSymbolAddress((void**)&sc2, g_scale2);
    cudaGetSymbolAddress((void**)&sf2, g_shift2);
    cudaGetSymbolAddress((void**)&sf3, g_shift3);

    prep_kernel<<<PREP_GRID, 256>>>(p2, p3, p4, p5, rois,
                                    conv1_w, conv2_w, logits_w, bbox_w,
                                    conv1_b, bn1_g, bn1_b, bn1_m, bn1_v,
                                    conv2_b, bn2_g, bn2_b, bn2_m, bn2_v,
                                    logits_b, bbox_b);

    {
        dim3 grid1(HID / 128, MPAD / 128);     // (8, 16)
        gemm_hmma_kernel<<<grid1, 256>>>(a1, b1, K1I, sc1, sf1, nullptr, a2, 1);
        gemm_hmma_kernel<<<grid1, 256>>>(a2, b2, K2I, sc2, sf2, nullptr, a3, 1);
        dim3 grid3(NHEADP / 128, MPAD / 128);  // (4, 16)
        gemm_hmma_kernel<<<grid3, 256>>>(a3, w3, K2I, nullptr, sf3, out, nullptr, 2);
    }

    softmax_kernel<<<(N_ROIS + 3) / 4, 128>>>(out);
}